// round 1
// baseline (speedup 1.0000x reference)
#include <cuda_runtime.h>

// Problem constants
#define BATCH   2
#define HH      256
#define WWID    256
#define CPL     32          // channels per plane
#define NPTS    (2*16384*32)  // 1,048,576 points
#define HID     64
#define OUTC    33

// Transposed triplane scratch: (B*3, H, W, 32ch) channel-last, 50.3 MB
__device__ float g_tp[(size_t)BATCH * 3 * HH * WWID * CPL];

// ---------------------------------------------------------------------------
// Kernel 1: transpose (B, 96, H, W) -> (B*3, H, W, 32)
// One block per (b, plane, y) row-slice: reads 32x256 coalesced over x,
// writes 256x32 contiguous (channel-last).
// ---------------------------------------------------------------------------
__global__ void transpose_k(const float* __restrict__ tri) {
    __shared__ float sh[32][257];
    int slice = blockIdx.x;         // (bp)*256 + y, bp in [0,6)
    int y  = slice & 255;
    int bp = slice >> 8;
    int tx = threadIdx.x;           // 0..255

    const float* src = tri + (size_t)bp * 32 * 65536 + (size_t)y * 256;
    #pragma unroll
    for (int c = 0; c < 32; c++)
        sh[c][tx] = src[(size_t)c * 65536 + tx];
    __syncthreads();

    float* dst = g_tp + ((size_t)bp * 65536 + (size_t)y * 256) * 32;
    #pragma unroll
    for (int i = 0; i < 32; i++) {
        int x = i * 8 + (tx >> 5);
        int c = tx & 31;
        dst[x * 32 + c] = sh[c][x];   // consecutive threads -> consecutive addrs
    }
}

// ---------------------------------------------------------------------------
// Kernel 2: sample + MLP. 256 threads/block, 256 points/block.
//   Phase A (sampling): 8 lanes per point, each owns 4 channels (float4),
//     accumulates 3 planes x 4 bilinear corners -> shared feat[256][33].
//   Phase B (MLP): 1 thread per point. Weights in shared (float4 broadcast).
//     h0 in regs; layer2 streamed per h1 element to bound register pressure.
//   Phase C: coalesced copy-out via shared staging.
// ---------------------------------------------------------------------------
__device__ __forceinline__ float lrelu(float v) { return fmaxf(v, 0.01f * v); }

// shared layout (floats):
//   sW0: [0,2048)  sW1: [2048,6144)  sW2(64x36 padded): [6144,8448)
//   sb0: [8448,8512) sb1: [8512,8576) sb2(pad 40): [8576,8616)
//   spt: [8616,9384)  sft(256x33): [9384,17832)
#define SMEM_FLOATS 17832

__global__ __launch_bounds__(256, 2) void decode_k(
    const float* __restrict__ pts,
    const float* __restrict__ W0, const float* __restrict__ b0,
    const float* __restrict__ W1, const float* __restrict__ b1,
    const float* __restrict__ W2, const float* __restrict__ b2,
    float* __restrict__ out)
{
    extern __shared__ float sm[];
    float* sW0 = sm;
    float* sW1 = sm + 2048;
    float* sW2 = sm + 6144;
    float* sb0 = sm + 8448;
    float* sb1 = sm + 8512;
    float* sb2 = sm + 8576;
    float* spt = sm + 8616;
    float* sft = sm + 9384;

    int tid = threadIdx.x;
    int n0  = blockIdx.x << 8;      // first point of this block

    // ---- load weights / biases / points into shared ----
    for (int i = tid; i < 2048; i += 256) sW0[i] = W0[i];
    for (int i = tid; i < 4096; i += 256) sW1[i] = W1[i];
    for (int i = tid; i < 64 * 36; i += 256) {
        int j = i / 36, o = i - j * 36;
        sW2[i] = (o < OUTC) ? W2[j * OUTC + o] : 0.f;
    }
    if (tid < 64) { sb0[tid] = b0[tid]; sb1[tid] = b1[tid]; }
    if (tid < 40) sb2[tid] = (tid < OUTC) ? b2[tid] : 0.f;
    for (int i = tid; i < 768; i += 256) spt[i] = pts[(size_t)n0 * 3 + i];
    __syncthreads();

    int bb = n0 >> 19;                           // batch (VV*S = 2^19)
    const float* plane_base = g_tp + (size_t)bb * 3 * 2097152;

    // ---- Phase A: sampling ----
    int cg = tid & 7;        // channel group (4 ch)
    int p0 = tid >> 3;       // 0..31
    #pragma unroll 1
    for (int pass = 0; pass < 8; pass++) {
        int pl = pass * 32 + p0;
        float px = spt[pl * 3 + 0];
        float py = spt[pl * 3 + 1];
        float pz = spt[pl * 3 + 2];
        float ax = 0.f, ay = 0.f, az = 0.f, aw = 0.f;
        #pragma unroll
        for (int plane = 0; plane < 3; plane++) {
            float gx = (plane == 2) ? py : px;    // xy, xz, yz
            float gy = (plane == 0) ? py : pz;
            float fx = fmaf(gx, 128.f, 127.5f);
            float fy = fmaf(gy, 128.f, 127.5f);
            float x0f = floorf(fx), y0f = floorf(fy);
            float wx = fx - x0f, wy = fy - y0f;
            int ix0 = (int)x0f, iy0 = (int)y0f;
            float w00 = (1.f - wx) * (1.f - wy);
            float w10 = wx * (1.f - wy);
            float w01 = (1.f - wx) * wy;
            float w11 = wx * wy;
            const float* pb = plane_base + (size_t)plane * 2097152 + cg * 4;
            #pragma unroll
            for (int k = 0; k < 4; k++) {
                int ix = ix0 + (k & 1);
                int iy = iy0 + (k >> 1);
                float w = (k == 0) ? w00 : (k == 1) ? w10 : (k == 2) ? w01 : w11;
                if ((unsigned)ix < 256u && (unsigned)iy < 256u) {
                    const float4 v = *(const float4*)(pb + ((size_t)((iy << 8) + ix)) * 32);
                    ax = fmaf(w, v.x, ax);
                    ay = fmaf(w, v.y, ay);
                    az = fmaf(w, v.z, az);
                    aw = fmaf(w, v.w, aw);
                }
            }
        }
        float* f = sft + pl * 33 + cg * 4;
        f[0] = ax; f[1] = ay; f[2] = az; f[3] = aw;
    }
    __syncthreads();

    // ---- Phase B: MLP, one point per thread ----
    {
        const float* frow = sft + tid * 33;
        const float4* W0v = (const float4*)sW0;
        const float4* W1v = (const float4*)sW1;
        const float4* W2v = (const float4*)sW2;
        const float4* b0v = (const float4*)sb0;
        const float4* b1v = (const float4*)sb1;
        const float4* b2v = (const float4*)sb2;

        // layer 0: 32 -> 64, accumulators in 16 float4 regs
        float4 h0a[16];
        #pragma unroll
        for (int j = 0; j < 16; j++) h0a[j] = b0v[j];
        #pragma unroll 1
        for (int c = 0; c < 32; c++) {
            float fc = frow[c];
            const float4* wr = W0v + c * 16;
            #pragma unroll
            for (int j = 0; j < 16; j++) {
                float4 w = wr[j];
                h0a[j].x = fmaf(fc, w.x, h0a[j].x);
                h0a[j].y = fmaf(fc, w.y, h0a[j].y);
                h0a[j].z = fmaf(fc, w.z, h0a[j].z);
                h0a[j].w = fmaf(fc, w.w, h0a[j].w);
            }
        }
        float h0[64];
        #pragma unroll
        for (int j = 0; j < 16; j++) {
            h0[4 * j + 0] = lrelu(h0a[j].x);
            h0[4 * j + 1] = lrelu(h0a[j].y);
            h0[4 * j + 2] = lrelu(h0a[j].z);
            h0[4 * j + 3] = lrelu(h0a[j].w);
        }

        // layer 1 + streamed layer 2
        float4 oa[9];
        #pragma unroll
        for (int o = 0; o < 9; o++) oa[o] = b2v[o];

        #pragma unroll 1
        for (int j4 = 0; j4 < 16; j4++) {
            float4 a = b1v[j4];
            const float4* wc = W1v + j4;
            #pragma unroll
            for (int c = 0; c < 64; c++) {
                float4 w = wc[c * 16];
                a.x = fmaf(h0[c], w.x, a.x);
                a.y = fmaf(h0[c], w.y, a.y);
                a.z = fmaf(h0[c], w.z, a.z);
                a.w = fmaf(h0[c], w.w, a.w);
            }
            float h1x = lrelu(a.x), h1y = lrelu(a.y);
            float h1z = lrelu(a.z), h1w = lrelu(a.w);
            const float4* r0 = W2v + (size_t)(4 * j4 + 0) * 9;
            const float4* r1 = W2v + (size_t)(4 * j4 + 1) * 9;
            const float4* r2 = W2v + (size_t)(4 * j4 + 2) * 9;
            const float4* r3 = W2v + (size_t)(4 * j4 + 3) * 9;
            #pragma unroll
            for (int o = 0; o < 9; o++) {
                float4 wa = r0[o], wb = r1[o], wcx = r2[o], wd = r3[o];
                oa[o].x = fmaf(h1x, wa.x, oa[o].x);
                oa[o].y = fmaf(h1x, wa.y, oa[o].y);
                oa[o].z = fmaf(h1x, wa.z, oa[o].z);
                oa[o].w = fmaf(h1x, wa.w, oa[o].w);
                oa[o].x = fmaf(h1y, wb.x, oa[o].x);
                oa[o].y = fmaf(h1y, wb.y, oa[o].y);
                oa[o].z = fmaf(h1y, wb.z, oa[o].z);
                oa[o].w = fmaf(h1y, wb.w, oa[o].w);
                oa[o].x = fmaf(h1z, wcx.x, oa[o].x);
                oa[o].y = fmaf(h1z, wcx.y, oa[o].y);
                oa[o].z = fmaf(h1z, wcx.z, oa[o].z);
                oa[o].w = fmaf(h1z, wcx.w, oa[o].w);
                oa[o].x = fmaf(h1w, wd.x, oa[o].x);
                oa[o].y = fmaf(h1w, wd.y, oa[o].y);
                oa[o].z = fmaf(h1w, wd.z, oa[o].z);
                oa[o].w = fmaf(h1w, wd.w, oa[o].w);
            }
        }

        // stage outputs into own feat row (only this thread touches it)
        float* orow = sft + tid * 33;
        #pragma unroll
        for (int o4 = 0; o4 < 9; o4++) {
            float v0 = oa[o4].x, v1 = oa[o4].y, v2 = oa[o4].z, v3 = oa[o4].w;
            int ob = o4 * 4;
            if (ob + 0 < OUTC) orow[ob + 0] = v0;
            if (ob + 1 < OUTC) orow[ob + 1] = v1;
            if (ob + 2 < OUTC) orow[ob + 2] = v2;
            if (ob + 3 < OUTC) orow[ob + 3] = v3;
        }
    }
    __syncthreads();

    // ---- Phase C: coalesced copy-out (256 pts * 33 floats = 2112 float4) ----
    float4*       dst = (float4*)(out + (size_t)n0 * OUTC);
    const float4* srcv = (const float4*)sft;
    for (int i = tid; i < 2112; i += 256)
        dst[i] = srcv[i];
}

// ---------------------------------------------------------------------------
extern "C" void kernel_launch(void* const* d_in, const int* in_sizes, int n_in,
                              void* d_out, int out_size) {
    const float* tri = (const float*)d_in[0];
    const float* pts = (const float*)d_in[1];
    const float* W0  = (const float*)d_in[2];
    const float* b0  = (const float*)d_in[3];
    const float* W1  = (const float*)d_in[4];
    const float* b1  = (const float*)d_in[5];
    const float* W2  = (const float*)d_in[6];
    const float* b2  = (const float*)d_in[7];
    float* out = (float*)d_out;

    cudaFuncSetAttribute(decode_k, cudaFuncAttributeMaxDynamicSharedMemorySize,
                         SMEM_FLOATS * 4);

    transpose_k<<<BATCH * 3 * HH, 256>>>(tri);
    decode_k<<<NPTS / 256, 256, SMEM_FLOATS * 4>>>(pts, W0, b0, W1, b1, W2, b2, out);
}